// round 16
// baseline (speedup 1.0000x reference)
#include <cuda_runtime.h>
#include <math.h>

#define B_   8
#define S_   4096
#define H_   1024
#define R_   (B_ * H_)
#define CAP  128
#define TAU_LG2   4.76107544f     /* 3.3 / ln2 */
#define INV_LN2   1.44269504f

// ---------------- device scratch (zero-initialized at load; kernels restore) ----------------
__device__ float2 g_buf[R_ * CAP];   // survivor (score, value) per row
__device__ int    g_cnt[R_];
__device__ float  g_pooled[R_];
__device__ int    g_ticket[256];     // per (b, h-chunk) completion counters

__device__ __forceinline__ float neg_inf() { return __int_as_float(0xff800000); }

__device__ __forceinline__ void flt_test(float x, float g, int r) {
    float sc = fmaf(g, INV_LN2, __log2f(x));  // NaN (x<0) / -inf (x==0): never > TAU
    if (sc > TAU_LG2) {
        int p = atomicAdd(&g_cnt[r], 1);
        if (p < CAP) g_buf[r * CAP + p] = make_float2(sc, x);
    }
}

// warp-cooperative top-8 over survivors of one row (+ exact fallback).
// Scratch reads via __ldcg (L2-direct); producers' stores live in L2.
__device__ void warp_select_row(int row, int lane,
                                const float* __restrict__ hidden,
                                const float* __restrict__ gumbel) {
    const float NI = neg_inf();
    int cnt = __ldcg(&g_cnt[row]);
    if (lane == 0) g_cnt[row] = 0;           // restore for next graph replay

    float sum = 0.f;

    if (cnt >= 8 && cnt <= CAP) {
        float sc0 = NI, sc1 = NI, sc2 = NI, sc3 = NI;
        float v0 = 0.f, v1 = 0.f, v2 = 0.f, v3 = 0.f;
        int base = row * CAP;
        if (lane      < cnt) { float2 c = __ldcg(&g_buf[base + lane]);      sc0 = c.x; v0 = c.y; }
        if (lane + 32 < cnt) { float2 c = __ldcg(&g_buf[base + lane + 32]); sc1 = c.x; v1 = c.y; }
        if (lane + 64 < cnt) { float2 c = __ldcg(&g_buf[base + lane + 64]); sc2 = c.x; v2 = c.y; }
        if (lane + 96 < cnt) { float2 c = __ldcg(&g_buf[base + lane + 96]); sc3 = c.x; v3 = c.y; }

        for (int round = 0; round < 8; ++round) {
            float bs = sc0, bv = v0; int bi = 0;
            if (sc1 > bs) { bs = sc1; bv = v1; bi = 1; }
            if (sc2 > bs) { bs = sc2; bv = v2; bi = 2; }
            if (sc3 > bs) { bs = sc3; bv = v3; bi = 3; }
            float m = bs;
#pragma unroll
            for (int off = 16; off > 0; off >>= 1)
                m = fmaxf(m, __shfl_xor_sync(0xffffffffu, m, off));
            unsigned ball = __ballot_sync(0xffffffffu, bs == m);
            int src = __ffs(ball) - 1;
            sum += __shfl_sync(0xffffffffu, bv, src);
            if (lane == src) {
                if      (bi == 0) sc0 = NI;
                else if (bi == 1) sc1 = NI;
                else if (bi == 2) sc2 = NI;
                else              sc3 = NI;
            }
        }
    } else {
        // exact fallback (rare; expected never): warp rescans the full row
        int b = row >> 10;
        int h = row & (H_ - 1);
        const float* hp = hidden + (size_t)b * S_ * H_ + h;
        const float* gp = gumbel + (size_t)row * S_;

        float lsc[8], lv[8];
#pragma unroll
        for (int j = 0; j < 8; ++j) { lsc[j] = NI; lv[j] = 0.f; }

        for (int s = lane; s < S_; s += 32) {
            float x = hp[(size_t)s * H_];
            float g = gp[s];
            float sc = (x > 0.f) ? fmaf(g, INV_LN2, __log2f(x)) : NI;
            if (sc > lsc[7]) {
                lsc[7] = sc; lv[7] = x;
#pragma unroll
                for (int j = 7; j > 0; --j) {
                    if (lsc[j] > lsc[j - 1]) {
                        float ts = lsc[j]; lsc[j] = lsc[j - 1]; lsc[j - 1] = ts;
                        float tv = lv[j];  lv[j]  = lv[j - 1];  lv[j - 1]  = tv;
                    }
                }
            }
        }
        int ptr = 0;
        for (int round = 0; round < 8; ++round) {
            float cand = NI, cval = 0.f;
#pragma unroll
            for (int j = 0; j < 8; ++j)
                if (j == ptr) { cand = lsc[j]; cval = lv[j]; }
            float m = cand;
#pragma unroll
            for (int off = 16; off > 0; off >>= 1)
                m = fmaxf(m, __shfl_xor_sync(0xffffffffu, m, off));
            unsigned ball = __ballot_sync(0xffffffffu, (cand == m) && (ptr < 8));
            if (ball == 0u) continue;        // remaining are -inf: contributes 0 (matches ref)
            int src = __ffs(ball) - 1;
            sum += __shfl_sync(0xffffffffu, cval, src);
            if (lane == src) ptr++;
        }
    }

    if (lane == 0) g_pooled[row] = sum;
}

// ---------------- 1: streaming filter (R15) + fused select, release-only producers ----------------
// Producers publish with ONE atom.add.release.gpu (no acquire, no fence, no
// L1 invalidate: the R11/R13 160us regressions were 8192 gpu-scope
// acquires/fences -> per-block CCTL.IVALL drains). Only the 32nd arriver (256
// blocks total) issues a single fence.acq_rel.gpu (relaxed-read + acquire-
// fence upgrade) before reading survivors L2-direct.
__global__ __launch_bounds__(128) void k_filter(const float* __restrict__ hidden,
                                                const float* __restrict__ gumbel) {
    __shared__ float sg[4 * 32 * 32];        // 16 KB: one 32x32 tile per warp
    __shared__ int   s_last;

    int blk  = blockIdx.x;                   // 0..8191
    int sidx = blk & 31;                     // 32 s-chunks (of 128)
    int hidx = (blk >> 5) & 31;              // 32 h-chunks (of 32)
    int b    = blk >> 10;                    // 8 batches
    int w    = threadIdx.x >> 5;             // 4 warps
    int lane = threadIdx.x & 31;

    int s0 = sidx * 128 + w * 32;            // this warp's s window
    int h0 = hidx * 32;
    float* st = sg + w * 1024;               // this warp's tile

    // ---- phase A: gumbel [32h x 32s] -> smem transposed (warp-private) ----
    {
        int row4 = lane >> 3;                // 0..3 : h-row within group of 4
        int c    = lane & 7;                 // 0..7 : float4 chunk along s
        const float4* gb = (const float4*)(gumbel + ((size_t)(b * H_ + h0)) * S_ + s0);
        float4 gr[8];
#pragma unroll
        for (int a = 0; a < 8; ++a) {        // 8 instrs x (4 rows x 128B) : full lines
            int hl = a * 4 + row4;
            gr[a] = __ldcv(&gb[(size_t)hl * (S_ / 4) + c]);
        }
#pragma unroll
        for (int a = 0; a < 8; ++a) {
            int hl = a * 4 + row4;
            int sl = 4 * c;
            st[(sl + 0) * 32 + ((hl + sl + 0) & 31)] = gr[a].x;
            st[(sl + 1) * 32 + ((hl + sl + 1) & 31)] = gr[a].y;
            st[(sl + 2) * 32 + ((hl + sl + 2) & 31)] = gr[a].z;
            st[(sl + 3) * 32 + ((hl + sl + 3) & 31)] = gr[a].w;
        }
    }
    __syncwarp();

    // ---- phase B: hidden coalesced (lane = h), gumbel from smem ----
    const float* hbase = hidden + ((size_t)b * S_ + s0) * H_ + h0 + lane;
    int r = b * H_ + h0 + lane;

#pragma unroll
    for (int grp = 0; grp < 2; ++grp) {
        float xs[16];
#pragma unroll
        for (int j = 0; j < 16; ++j)
            xs[j] = __ldcv(&hbase[(size_t)(grp * 16 + j) * H_]);
#pragma unroll
        for (int j = 0; j < 16; ++j) {
            int sl = grp * 16 + j;
            float g = st[sl * 32 + ((lane + sl) & 31)];
            flt_test(xs[j], g, r);
        }
    }

    // ---- publish: release-only ticket; 32nd arriver becomes the selector ----
    __syncthreads();                         // block's writes complete (CTA scope)
    if (threadIdx.x == 0) {
        int t;
        asm volatile("atom.add.release.gpu.global.s32 %0, [%1], 1;"
                     : "=r"(t) : "l"(&g_ticket[b * 32 + hidx]) : "memory");
        s_last = (t == 31);
    }
    __syncthreads();
    if (!s_last) return;

    if (threadIdx.x == 0) {
        asm volatile("fence.acq_rel.gpu;" ::: "memory");  // acquire side: 256 total
        g_ticket[b * 32 + hidx] = 0;         // reset for next graph replay
    }
    __syncthreads();

    int row0 = b * H_ + h0;
#pragma unroll 1
    for (int rr = 0; rr < 8; ++rr)
        warp_select_row(row0 + w * 8 + rr, lane, hidden, gumbel);
}

// ---------------- 2: out = tanh(pooled @ W^T + bias) — warp-per-j, grid 256x128 ----------------
__global__ __launch_bounds__(128) void k_gemm(const float* __restrict__ W,
                                              const float* __restrict__ bias,
                                              float* __restrict__ out) {
    __shared__ float4 sp4[8 * 256];          // pooled as [bb][256 float4] = 32 KB

    int tid  = threadIdx.x;
    int w    = tid >> 5;
    int lane = tid & 31;

    // stage pooled: 2048 float4, 16 per thread (L2-hot source)
    const float4* gp4 = (const float4*)g_pooled;
#pragma unroll
    for (int k = 0; k < 16; ++k)
        sp4[tid + k * 128] = __ldcg(&gp4[tid + k * 128]);
    __syncthreads();

    int j = blockIdx.x * 4 + w;              // this warp's output feature

    const float4* W4 = (const float4*)(W + (size_t)j * H_);
    float4 wv[8];
#pragma unroll
    for (int it = 0; it < 8; ++it)
        wv[it] = __ldcs(&W4[it * 32 + lane]);

    float acc[8];
#pragma unroll
    for (int bb = 0; bb < 8; ++bb) acc[bb] = 0.f;

#pragma unroll
    for (int it = 0; it < 8; ++it) {
#pragma unroll
        for (int bb = 0; bb < 8; ++bb) {
            float4 p = sp4[bb * 256 + it * 32 + lane];
            acc[bb] += wv[it].x * p.x + wv[it].y * p.y
                     + wv[it].z * p.z + wv[it].w * p.w;
        }
    }
#pragma unroll
    for (int bb = 0; bb < 8; ++bb)
#pragma unroll
        for (int off = 16; off > 0; off >>= 1)
            acc[bb] += __shfl_xor_sync(0xffffffffu, acc[bb], off);

    float bj = bias[j];
#pragma unroll
    for (int bb = 0; bb < 8; ++bb)
        if (lane == bb) out[bb * H_ + j] = tanhf(acc[bb] + bj);
}

// ---------------- launch ----------------
extern "C" void kernel_launch(void* const* d_in, const int* in_sizes, int n_in,
                              void* d_out, int out_size) {
    const float* hidden = (const float*)d_in[0];
    const float* gumbel = (const float*)d_in[1];
    const float* W      = (const float*)d_in[2];
    const float* bias   = (const float*)d_in[3];
    float*       out    = (float*)d_out;
    (void)in_sizes; (void)n_in; (void)out_size;

    k_filter<<<8192, 128>>>(hidden, gumbel);
    k_gemm  <<<256,  128>>>(W, bias, out);
}

// round 17
// speedup vs baseline: 1.8144x; 1.8144x over previous
#include <cuda_runtime.h>
#include <math.h>

#define B_   8
#define S_   4096
#define H_   1024
#define R_   (B_ * H_)
#define CAP  128
#define TAU_LG2   4.76107544f     /* 3.3 / ln2 */
#define INV_LN2   1.44269504f

// ---------------- device scratch (zero-initialized at load; select restores) ----------------
__device__ float2 g_buf[R_ * CAP];   // survivor (score, value) per row
__device__ int    g_cnt[R_];
__device__ float  g_pooled[R_];

__device__ __forceinline__ float neg_inf() { return __int_as_float(0xff800000); }

__device__ __forceinline__ void flt_test(float x, float g, int r) {
    float sc = fmaf(g, INV_LN2, __log2f(x));  // NaN (x<0) / -inf (x==0): never > TAU
    if (sc > TAU_LG2) {
        int p = atomicAdd(&g_cnt[r], 1);
        if (p < CAP) g_buf[r * CAP + p] = make_float2(sc, x);
    }
}

// ---------------- 1: streaming filter — warp tiles, L1-bypass loads (R15, at BW floor) ----------------
__global__ __launch_bounds__(128) void k_filter(const float* __restrict__ hidden,
                                                const float* __restrict__ gumbel) {
    __shared__ float sg[4 * 32 * 32];        // 16 KB: one 32x32 tile per warp

    int blk  = blockIdx.x;                   // 0..8191
    int sidx = blk & 31;                     // 32 s-chunks (of 128)
    int hidx = (blk >> 5) & 31;              // 32 h-chunks (of 32)
    int b    = blk >> 10;                    // 8 batches
    int w    = threadIdx.x >> 5;             // 4 warps
    int lane = threadIdx.x & 31;

    int s0 = sidx * 128 + w * 32;            // this warp's s window
    int h0 = hidx * 32;
    float* st = sg + w * 1024;               // this warp's tile

    // ---- phase A: gumbel [32h x 32s] -> smem transposed (warp-private) ----
    {
        int row4 = lane >> 3;                // 0..3 : h-row within group of 4
        int c    = lane & 7;                 // 0..7 : float4 chunk along s
        const float4* gb = (const float4*)(gumbel + ((size_t)(b * H_ + h0)) * S_ + s0);
        float4 gr[8];
#pragma unroll
        for (int a = 0; a < 8; ++a) {        // 8 instrs x (4 rows x 128B) : full lines
            int hl = a * 4 + row4;
            gr[a] = __ldcv(&gb[(size_t)hl * (S_ / 4) + c]);
        }
#pragma unroll
        for (int a = 0; a < 8; ++a) {
            int hl = a * 4 + row4;
            int sl = 4 * c;
            st[(sl + 0) * 32 + ((hl + sl + 0) & 31)] = gr[a].x;
            st[(sl + 1) * 32 + ((hl + sl + 1) & 31)] = gr[a].y;
            st[(sl + 2) * 32 + ((hl + sl + 2) & 31)] = gr[a].z;
            st[(sl + 3) * 32 + ((hl + sl + 3) & 31)] = gr[a].w;
        }
    }
    __syncwarp();

    // ---- phase B: hidden coalesced (lane = h), gumbel from smem ----
    const float* hbase = hidden + ((size_t)b * S_ + s0) * H_ + h0 + lane;
    int r = b * H_ + h0 + lane;

#pragma unroll
    for (int grp = 0; grp < 2; ++grp) {
        float xs[16];
#pragma unroll
        for (int j = 0; j < 16; ++j)
            xs[j] = __ldcv(&hbase[(size_t)(grp * 16 + j) * H_]);
#pragma unroll
        for (int j = 0; j < 16; ++j) {
            int sl = grp * 16 + j;
            float g = st[sl * 32 + ((lane + sl) & 31)];
            flt_test(xs[j], g, r);
        }
    }
}

// ---------------- 2: per-row top-8 over survivors (+ inline exact fallback) ----------------
__global__ __launch_bounds__(256) void k_select(const float* __restrict__ hidden,
                                                const float* __restrict__ gumbel) {
    int row  = (blockIdx.x * blockDim.x + threadIdx.x) >> 5;
    int lane = threadIdx.x & 31;
    if (row >= R_) return;

    const float NI = neg_inf();
    int cnt = g_cnt[row];
    if (lane == 0) g_cnt[row] = 0;           // restore for next graph replay

    float sum = 0.f;

    if (cnt >= 8 && cnt <= CAP) {
        float sc0 = NI, sc1 = NI, sc2 = NI, sc3 = NI;
        float v0 = 0.f, v1 = 0.f, v2 = 0.f, v3 = 0.f;
        int base = row * CAP;
        if (lane      < cnt) { float2 c = g_buf[base + lane];      sc0 = c.x; v0 = c.y; }
        if (lane + 32 < cnt) { float2 c = g_buf[base + lane + 32]; sc1 = c.x; v1 = c.y; }
        if (lane + 64 < cnt) { float2 c = g_buf[base + lane + 64]; sc2 = c.x; v2 = c.y; }
        if (lane + 96 < cnt) { float2 c = g_buf[base + lane + 96]; sc3 = c.x; v3 = c.y; }

        for (int round = 0; round < 8; ++round) {
            float bs = sc0, bv = v0; int bi = 0;
            if (sc1 > bs) { bs = sc1; bv = v1; bi = 1; }
            if (sc2 > bs) { bs = sc2; bv = v2; bi = 2; }
            if (sc3 > bs) { bs = sc3; bv = v3; bi = 3; }
            float m = bs;
#pragma unroll
            for (int off = 16; off > 0; off >>= 1)
                m = fmaxf(m, __shfl_xor_sync(0xffffffffu, m, off));
            unsigned ball = __ballot_sync(0xffffffffu, bs == m);
            int src = __ffs(ball) - 1;
            sum += __shfl_sync(0xffffffffu, bv, src);
            if (lane == src) {
                if      (bi == 0) sc0 = NI;
                else if (bi == 1) sc1 = NI;
                else if (bi == 2) sc2 = NI;
                else              sc3 = NI;
            }
        }
    } else {
        // exact fallback (rare; expected never): warp rescans the full row
        int b = row >> 10;
        int h = row & (H_ - 1);
        const float* hp = hidden + (size_t)b * S_ * H_ + h;
        const float* gp = gumbel + (size_t)row * S_;

        float lsc[8], lv[8];
#pragma unroll
        for (int j = 0; j < 8; ++j) { lsc[j] = NI; lv[j] = 0.f; }

        for (int s = lane; s < S_; s += 32) {
            float x = hp[(size_t)s * H_];
            float g = gp[s];
            float sc = (x > 0.f) ? fmaf(g, INV_LN2, __log2f(x)) : NI;
            if (sc > lsc[7]) {
                lsc[7] = sc; lv[7] = x;
#pragma unroll
                for (int j = 7; j > 0; --j) {
                    if (lsc[j] > lsc[j - 1]) {
                        float ts = lsc[j]; lsc[j] = lsc[j - 1]; lsc[j - 1] = ts;
                        float tv = lv[j];  lv[j]  = lv[j - 1];  lv[j - 1]  = tv;
                    }
                }
            }
        }
        int ptr = 0;
        for (int round = 0; round < 8; ++round) {
            float cand = NI, cval = 0.f;
#pragma unroll
            for (int j = 0; j < 8; ++j)
                if (j == ptr) { cand = lsc[j]; cval = lv[j]; }
            float m = cand;
#pragma unroll
            for (int off = 16; off > 0; off >>= 1)
                m = fmaxf(m, __shfl_xor_sync(0xffffffffu, m, off));
            unsigned ball = __ballot_sync(0xffffffffu, (cand == m) && (ptr < 8));
            if (ball == 0u) continue;        // remaining are -inf: contributes 0 (matches ref)
            int src = __ffs(ball) - 1;
            sum += __shfl_sync(0xffffffffu, cval, src);
            if (lane == src) ptr++;
        }
    }

    if (lane == 0) g_pooled[row] = sum;
}

// ---------------- 3: out = tanh(pooled @ W^T + bias) — 2 j per warp, W-first ----------------
// Grid 128 x 128: all blocks resident, 512 warps x 16 LDG.128 = the entire 4MB
// of W in flight at once. W loads issue BEFORE the pooled staging + sync, so
// their DRAM latency overlaps the staging phase instead of following it.
__global__ __launch_bounds__(128) void k_gemm(const float* __restrict__ W,
                                              const float* __restrict__ bias,
                                              float* __restrict__ out) {
    __shared__ float4 sp4[8 * 256];          // pooled as [bb][256 float4] = 32 KB

    int tid  = threadIdx.x;
    int w    = tid >> 5;
    int lane = tid & 31;
    int j0   = blockIdx.x * 8 + w * 2;       // this warp's two output features

    // ---- W loads first: 16 independent LDG.128 per lane, nothing blocks them ----
    const float4* W4a = (const float4*)(W + (size_t)j0 * H_);
    const float4* W4b = (const float4*)(W + (size_t)(j0 + 1) * H_);
    float4 wa[8], wb[8];
#pragma unroll
    for (int it = 0; it < 8; ++it)
        wa[it] = __ldcs(&W4a[it * 32 + lane]);
#pragma unroll
    for (int it = 0; it < 8; ++it)
        wb[it] = __ldcs(&W4b[it * 32 + lane]);

    // ---- stage pooled (L2-hot) while W is in flight ----
    const float4* gp4 = (const float4*)g_pooled;
#pragma unroll
    for (int k = 0; k < 16; ++k)
        sp4[tid + k * 128] = gp4[tid + k * 128];
    __syncthreads();

    float acca[8], accb[8];
#pragma unroll
    for (int bb = 0; bb < 8; ++bb) { acca[bb] = 0.f; accb[bb] = 0.f; }

#pragma unroll
    for (int it = 0; it < 8; ++it) {
#pragma unroll
        for (int bb = 0; bb < 8; ++bb) {
            float4 p = sp4[bb * 256 + it * 32 + lane];
            acca[bb] += wa[it].x * p.x + wa[it].y * p.y
                      + wa[it].z * p.z + wa[it].w * p.w;
            accb[bb] += wb[it].x * p.x + wb[it].y * p.y
                      + wb[it].z * p.z + wb[it].w * p.w;
        }
    }
#pragma unroll
    for (int bb = 0; bb < 8; ++bb) {
#pragma unroll
        for (int off = 16; off > 0; off >>= 1) {
            acca[bb] += __shfl_xor_sync(0xffffffffu, acca[bb], off);
            accb[bb] += __shfl_xor_sync(0xffffffffu, accb[bb], off);
        }
    }

    float bja = bias[j0];
    float bjb = bias[j0 + 1];
#pragma unroll
    for (int bb = 0; bb < 8; ++bb) {
        if (lane == bb) {
            out[bb * H_ + j0]     = tanhf(acca[bb] + bja);
            out[bb * H_ + j0 + 1] = tanhf(accb[bb] + bjb);
        }
    }
}

// ---------------- launch ----------------
extern "C" void kernel_launch(void* const* d_in, const int* in_sizes, int n_in,
                              void* d_out, int out_size) {
    const float* hidden = (const float*)d_in[0];
    const float* gumbel = (const float*)d_in[1];
    const float* W      = (const float*)d_in[2];
    const float* bias   = (const float*)d_in[3];
    float*       out    = (float*)d_out;
    (void)in_sizes; (void)n_in; (void)out_size;

    k_filter<<<8192, 128>>>(hidden, gumbel);
    k_select<<<1024, 256>>>(hidden, gumbel);
    k_gemm  <<<128,  128>>>(W, bias, out);
}